// round 2
// baseline (speedup 1.0000x reference)
#include <cuda_runtime.h>
#include <math.h>

// ---------------------------------------------------------------------------
// CLFormer fused implementation for GB300 (sm_103a)
//
// Shapes (fixed by the problem):
//   B=32, C=32, L=16384, HEADS=4 (dh=8), NB=3 blocks, DOUT=10
//
// Layout convention: all big activations kept in [B][C][L] (channel-major)
// so every global access is a perfectly coalesced per-channel row.
// The h buffer is updated IN PLACE by the token kernels (each thread owns
// one token: read 32 ch, compute, write 32 ch) -> only 64MB of scratch,
// which stays L2-resident across kernels.
//
// Per block:
//   - k-softmax over L needs a global reduction -> chunked partial stats
//     (online max, S[d]=sum exp, M[d][e]=sum exp*h) + tiny combine kernel
//     producing kv[b][h][8][8].
//   - token kernel: q-softmax (over dh) @ kv, FC1+GELU, FC2+GELU, and it
//     FUSES the partial-stats computation for the NEXT block (or the
//     mean-pool partials for the last block).
// ---------------------------------------------------------------------------

#define Bn   32
#define Cn   32
#define Ln   16384
#define TLn  512              // tokens per CTA (chunk)
#define NCHn (Ln / TLn)       // 32 chunks per batch row
#define NTHn 128              // threads per CTA
#define NGRPn (TLn / NTHn)    // 4 groups of 128 tokens

// Scratch (device globals; no allocation at runtime)
__device__ float g_h[(size_t)Bn * Cn * Ln];        // 64 MB activation buffer (in-place)
__device__ float g_part[Bn * NCHn * 320];          // per-(b,chunk): 32 m | 32 S | 256 M
__device__ float g_kv[Bn * 256];                   // kv[b][head][d][e]
__device__ float g_poolpart[Bn * NCHn * 32];       // pooling partial sums

__device__ __forceinline__ float gelu_f(float v) {
    return 0.5f * v * (1.0f + erff(v * 0.7071067811865475f));
}

// Shared-memory block for chunk-local softmax stats
struct StatsSh {
    float hSh[NTHn * 33];   // token-major h values (padded stride 33: conflict-free)
    float eSh[NTHn * 33];   // exp(h - chunk_max)
    float sm[32];           // running per-channel max
    float sS[32];           // running per-channel exp-sum
    float sM[256];          // running M[head][d][e]
    float snewm[32];
    float sr[32];           // rescale factors
    float wred[4 * 32];     // per-warp reduction scratch
};

__device__ __forceinline__ void stats_init(StatsSh* s, int tid) {
    if (tid < 32) { s->sm[tid] = -1e30f; s->sS[tid] = 0.f; }
    s->sM[tid] = 0.f;
    s->sM[tid + 128] = 0.f;
}

// All 128 threads participate; hv = this thread's token values (32 channels).
__device__ __forceinline__ void stats_group(StatsSh* s, const float (&hv)[32],
                                            int tid, int lane, int wid) {
    // stage token values
#pragma unroll
    for (int c = 0; c < 32; c++) s->hSh[tid * 33 + c] = hv[c];

    // per-channel max across the 128 tokens of this group
#pragma unroll
    for (int c = 0; c < 32; c++) {
        float v = hv[c];
#pragma unroll
        for (int o = 16; o > 0; o >>= 1)
            v = fmaxf(v, __shfl_xor_sync(0xffffffffu, v, o));
        if (lane == 0) s->wred[wid * 32 + c] = v;
    }
    __syncthreads();
    if (tid < 32) {
        float gm = fmaxf(fmaxf(s->wred[tid], s->wred[32 + tid]),
                         fmaxf(s->wred[64 + tid], s->wred[96 + tid]));
        float om = s->sm[tid];
        float nm = fmaxf(om, gm);
        s->sm[tid] = nm;
        s->snewm[tid] = nm;
        s->sr[tid] = __expf(om - nm);   // 0 on first group (om=-1e30)
    }
    __syncthreads();

    // exponentials
#pragma unroll
    for (int c = 0; c < 32; c++) s->eSh[tid * 33 + c] = __expf(hv[c] - s->snewm[c]);
    __syncthreads();

    // M / S accumulation: thread owns entries tid and tid+128
    {
        const int u0 = tid;
        const int cd0 = ((u0 >> 6) << 3) | ((u0 >> 3) & 7);
        const int ce0 = ((u0 >> 6) << 3) | (u0 & 7);
        const int cd1 = cd0 + 16;
        const int ce1 = ce0 + 16;
        float m0 = s->sM[u0] * s->sr[cd0];
        float m1 = s->sM[u0 + 128] * s->sr[cd1];
        float s0 = 0.f, s1 = 0.f;
#pragma unroll 4
        for (int l = 0; l < NTHn; l++) {
            float e0 = s->eSh[l * 33 + cd0];
            float e1 = s->eSh[l * 33 + cd1];
            m0 += e0 * s->hSh[l * 33 + ce0];
            m1 += e1 * s->hSh[l * 33 + ce1];
            s0 += e0;
            s1 += e1;
        }
        s->sM[u0] = m0;
        s->sM[u0 + 128] = m1;
        if ((tid & 7) == 0) {   // e==0 threads own S[cd]
            s->sS[cd0] = s->sS[cd0] * s->sr[cd0] + s0;
            s->sS[cd1] = s->sS[cd1] * s->sr[cd1] + s1;
        }
    }
    __syncthreads();
}

__device__ __forceinline__ void stats_writeout(StatsSh* s, int tid, int b, int ch) {
    float* pp = g_part + ((size_t)b * NCHn + ch) * 320;
    if (tid < 32) { pp[tid] = s->sm[tid]; pp[32 + tid] = s->sS[tid]; }
    pp[64 + tid] = s->sM[tid];
    pp[192 + tid] = s->sM[tid + 128];
}

// ---------------------------------------------------------------------------
// Kernel 1: stats over the raw input x (for block 0's kv)
// ---------------------------------------------------------------------------
__global__ __launch_bounds__(NTHn) void stats_x_kernel(const float* __restrict__ x) {
    __shared__ StatsSh s;
    int tid = threadIdx.x, lane = tid & 31, wid = tid >> 5;
    int b = blockIdx.y, ch = blockIdx.x;
    stats_init(&s, tid);
    __syncthreads();
    const float* xb = x + (size_t)b * Cn * Ln;
    for (int g = 0; g < NGRPn; g++) {
        int l = ch * TLn + g * NTHn + tid;
        float h[32];
#pragma unroll
        for (int c = 0; c < 32; c++) h[c] = xb[c * Ln + l];
        stats_group(&s, h, tid, lane, wid);
    }
    stats_writeout(&s, tid, b, ch);
}

// ---------------------------------------------------------------------------
// Kernel 2: combine chunk partials into kv[b][head][d][e]
// ---------------------------------------------------------------------------
__global__ __launch_bounds__(256) void combine_kernel() {
    int b = blockIdx.x, tid = threadIdx.x;
    __shared__ float gmax[32], Sg[32];
    const float* pb = g_part + (size_t)b * NCHn * 320;
    if (tid < 32) {
        float gm = -1e30f;
        for (int ch = 0; ch < NCHn; ch++) gm = fmaxf(gm, pb[ch * 320 + tid]);
        gmax[tid] = gm;
        float ss = 0.f;
        for (int ch = 0; ch < NCHn; ch++)
            ss += pb[ch * 320 + 32 + tid] * __expf(pb[ch * 320 + tid] - gm);
        Sg[tid] = ss;
    }
    __syncthreads();
    int cd = ((tid >> 6) << 3) | ((tid >> 3) & 7);
    float m = 0.f;
    for (int ch = 0; ch < NCHn; ch++)
        m += pb[ch * 320 + 64 + tid] * __expf(pb[ch * 320 + cd] - gmax[cd]);
    g_kv[b * 256 + tid] = m / Sg[cd];
}

// ---------------------------------------------------------------------------
// Kernel 3: per-token pass for one block.
//   FROM_X: read from x (else from g_h). LAST: accumulate pooling partials
//   instead of writing h + next-block stats.
// ---------------------------------------------------------------------------
template <bool FROM_X, bool LAST>
__global__ __launch_bounds__(NTHn) void token_kernel(
    const float* __restrict__ xin,
    const float* __restrict__ W1, const float* __restrict__ b1,
    const float* __restrict__ W2, const float* __restrict__ b2) {
    __shared__ StatsSh s;
    __shared__ float sW1[1024], sW2[1024], sb1[32], sb2[32], skv[256], spool[32];
    int tid = threadIdx.x, lane = tid & 31, wid = tid >> 5;
    int b = blockIdx.y, ch = blockIdx.x;

    for (int i = tid; i < 1024; i += NTHn) { sW1[i] = W1[i]; sW2[i] = W2[i]; }
    if (tid < 32) { sb1[tid] = b1[tid]; sb2[tid] = b2[tid]; spool[tid] = 0.f; }
    skv[tid] = g_kv[b * 256 + tid];
    skv[tid + 128] = g_kv[b * 256 + tid + 128];
    stats_init(&s, tid);
    __syncthreads();

    const float* inb = FROM_X ? (xin + (size_t)b * Cn * Ln) : (g_h + (size_t)b * Cn * Ln);
    float* outb = g_h + (size_t)b * Cn * Ln;

    for (int g = 0; g < NGRPn; g++) {
        int l = ch * TLn + g * NTHn + tid;
        float h[32];
#pragma unroll
        for (int c = 0; c < 32; c++) h[c] = inb[c * Ln + l];

        // ---- linear attention: q = softmax_dh(h); out = q @ kv (in place) ----
#pragma unroll
        for (int hd = 0; hd < 4; hd++) {
            const int base = hd * 8;
            float mx = h[base];
#pragma unroll
            for (int d = 1; d < 8; d++) mx = fmaxf(mx, h[base + d]);
            float es[8];
            float sum = 0.f;
#pragma unroll
            for (int d = 0; d < 8; d++) { es[d] = __expf(h[base + d] - mx); sum += es[d]; }
            float inv = 1.0f / sum;
            float acc[8];
#pragma unroll
            for (int e = 0; e < 8; e++) acc[e] = 0.f;
#pragma unroll
            for (int d = 0; d < 8; d++) {
                float q = es[d];
                const float4* kr = (const float4*)&skv[hd * 64 + d * 8];
                float4 k0 = kr[0], k1 = kr[1];
                acc[0] += q * k0.x; acc[1] += q * k0.y;
                acc[2] += q * k0.z; acc[3] += q * k0.w;
                acc[4] += q * k1.x; acc[5] += q * k1.y;
                acc[6] += q * k1.z; acc[7] += q * k1.w;
            }
#pragma unroll
            for (int e = 0; e < 8; e++) h[base + e] = acc[e] * inv;
        }

        // ---- FC1 + GELU ----
        float f[32];
#pragma unroll
        for (int j = 0; j < 32; j++) f[j] = sb1[j];
#pragma unroll
        for (int i = 0; i < 32; i++) {
            float ai = h[i];
            const float4* wr = (const float4*)&sW1[i * 32];
#pragma unroll
            for (int j4 = 0; j4 < 8; j4++) {
                float4 w = wr[j4];
                f[j4 * 4 + 0] += ai * w.x; f[j4 * 4 + 1] += ai * w.y;
                f[j4 * 4 + 2] += ai * w.z; f[j4 * 4 + 3] += ai * w.w;
            }
        }
#pragma unroll
        for (int j = 0; j < 32; j++) f[j] = gelu_f(f[j]);

        // ---- FC2 + GELU ----
#pragma unroll
        for (int j = 0; j < 32; j++) h[j] = sb2[j];
#pragma unroll
        for (int i = 0; i < 32; i++) {
            float ai = f[i];
            const float4* wr = (const float4*)&sW2[i * 32];
#pragma unroll
            for (int j4 = 0; j4 < 8; j4++) {
                float4 w = wr[j4];
                h[j4 * 4 + 0] += ai * w.x; h[j4 * 4 + 1] += ai * w.y;
                h[j4 * 4 + 2] += ai * w.z; h[j4 * 4 + 3] += ai * w.w;
            }
        }
#pragma unroll
        for (int j = 0; j < 32; j++) h[j] = gelu_f(h[j]);

        if (!LAST) {
            // write new h (in place) + fused next-block stats
#pragma unroll
            for (int c = 0; c < 32; c++) outb[c * Ln + l] = h[c];
            stats_group(&s, h, tid, lane, wid);
        } else {
            // fused mean-pool partials
#pragma unroll
            for (int c = 0; c < 32; c++) {
                float v = h[c];
#pragma unroll
                for (int o = 16; o > 0; o >>= 1)
                    v += __shfl_xor_sync(0xffffffffu, v, o);
                if (lane == 0) s.wred[wid * 32 + c] = v;
            }
            __syncthreads();
            if (tid < 32)
                spool[tid] += s.wred[tid] + s.wred[32 + tid] +
                              s.wred[64 + tid] + s.wred[96 + tid];
            __syncthreads();
        }
    }
    if (!LAST)
        stats_writeout(&s, tid, b, ch);
    else if (tid < 32)
        g_poolpart[((size_t)b * NCHn + ch) * 32 + tid] = spool[tid];
}

// ---------------------------------------------------------------------------
// Kernel 4: classifier head (pool-finish, Linear, BN(eval), GELU, Linear)
// ---------------------------------------------------------------------------
__global__ __launch_bounds__(32) void final_kernel(
    const float* __restrict__ Wh, const float* __restrict__ bh,
    const float* __restrict__ gamma, const float* __restrict__ beta,
    const float* __restrict__ mu, const float* __restrict__ var,
    const float* __restrict__ Wf, const float* __restrict__ bf,
    float* __restrict__ out) {
    int b = threadIdx.x;
    if (b >= Bn) return;
    float p[32];
#pragma unroll
    for (int c = 0; c < 32; c++) {
        float sum = 0.f;
        for (int ch = 0; ch < NCHn; ch++)
            sum += g_poolpart[((size_t)b * NCHn + ch) * 32 + c];
        p[c] = sum * (1.0f / (float)Ln);
    }
    float z[32];
#pragma unroll
    for (int j = 0; j < 32; j++) {
        float sv = bh[j];
#pragma unroll
        for (int c = 0; c < 32; c++) sv += p[c] * Wh[c * 32 + j];
        sv = (sv - mu[j]) * rsqrtf(var[j] + 1e-5f) * gamma[j] + beta[j];
        z[j] = gelu_f(sv);
    }
    for (int k = 0; k < 10; k++) {
        float sv = bf[k];
#pragma unroll
        for (int j = 0; j < 32; j++) sv += z[j] * Wf[j * 10 + k];
        out[b * 10 + k] = sv;
    }
}

// ---------------------------------------------------------------------------
// Launcher
// ---------------------------------------------------------------------------
extern "C" void kernel_launch(void* const* d_in, const int* in_sizes, int n_in,
                              void* d_out, int out_size) {
    const float* x    = (const float*)d_in[0];
    const float* fcW1 = (const float*)d_in[1];   // [3][32][32]
    const float* fcb1 = (const float*)d_in[2];   // [3][32]
    const float* fcW2 = (const float*)d_in[3];
    const float* fcb2 = (const float*)d_in[4];
    const float* Wh   = (const float*)d_in[5];
    const float* bh   = (const float*)d_in[6];
    const float* gam  = (const float*)d_in[7];
    const float* bet  = (const float*)d_in[8];
    const float* mu   = (const float*)d_in[9];
    const float* var  = (const float*)d_in[10];
    const float* Wf   = (const float*)d_in[11];
    const float* bf   = (const float*)d_in[12];
    float* out = (float*)d_out;

    dim3 grid(NCHn, Bn);

    // block 0 stats from x
    stats_x_kernel<<<grid, NTHn>>>(x);
    combine_kernel<<<Bn, 256>>>();
    // block 0 token pass (reads x, writes g_h, stats for block 1)
    token_kernel<true, false><<<grid, NTHn>>>(x, fcW1, fcb1, fcW2, fcb2);
    combine_kernel<<<Bn, 256>>>();
    // block 1 (in-place on g_h, stats for block 2)
    token_kernel<false, false><<<grid, NTHn>>>(nullptr, fcW1 + 1024, fcb1 + 32,
                                               fcW2 + 1024, fcb2 + 32);
    combine_kernel<<<Bn, 256>>>();
    // block 2 (pooling partials)
    token_kernel<false, true><<<grid, NTHn>>>(nullptr, fcW1 + 2048, fcb1 + 64,
                                              fcW2 + 2048, fcb2 + 64);
    final_kernel<<<1, 32>>>(Wh, bh, gam, bet, mu, var, Wf, bf, out);
}

// round 3
// speedup vs baseline: 1.3946x; 1.3946x over previous
#include <cuda_runtime.h>
#include <math.h>

// ---------------------------------------------------------------------------
// CLFormer v2 for GB300 (sm_103a).  B=32, C=32, L=16384, H=4(dh=8), NB=3.
// Changes vs v1: no online-max (fp32-safe), packed fma.rn.f32x2 FCs/attn/stats,
// register-resident stats rows, combine folded into token prologue (double-
// buffered partials), branch-free A&S erf GELU. 5 launches total.
// ---------------------------------------------------------------------------

#define Bn 32
#define Cn 32
#define Ln 16384
#define NCH 32          // chunks per batch row
#define CHT 512         // tokens per chunk
#define NTH 128
#define NGR 4           // groups of 128 tokens per chunk
#define HST 36          // smem h stride (floats), conflict-free & 16B-aligned

typedef unsigned long long u64;

__device__ float g_h[(size_t)Bn * Cn * Ln];     // 64MB activations (in place)
__device__ float g_partA[Bn * NCH * 288];       // per (b,ch): S[32] | M[256]
__device__ float g_partB[Bn * NCH * 288];
__device__ float g_pool[Bn * NCH * 32];

// ---- packed f32x2 helpers --------------------------------------------------
__device__ __forceinline__ u64 dup2(float a) {
    u64 r; asm("mov.b64 %0, {%1, %1};" : "=l"(r) : "f"(a)); return r;
}
__device__ __forceinline__ void fma2(u64& d, u64 a, u64 b) {
    asm("fma.rn.f32x2 %0, %1, %2, %0;" : "+l"(d) : "l"(a), "l"(b));
}
__device__ __forceinline__ float2 unpk(u64 v) {
    float2 f; asm("mov.b64 {%0, %1}, %2;" : "=f"(f.x), "=f"(f.y) : "l"(v)); return f;
}
__device__ __forceinline__ float frcp(float x) {
    float r; asm("rcp.approx.f32 %0, %1;" : "=f"(r) : "f"(x)); return r;
}

// GELU with A&S 7.1.26 erf (max abs err 1.5e-7), branch-free
__device__ __forceinline__ float gelu_f(float x) {
    float z = fabsf(x) * 0.7071067811865476f;
    float t = frcp(fmaf(0.3275911f, z, 1.0f));
    float p = t * fmaf(t, fmaf(t, fmaf(t, fmaf(t, 1.061405429f, -1.453152027f),
                  1.421413741f), -0.284496736f), 0.254829592f);
    float er = copysignf(fmaf(-p, __expf(-z * z), 1.0f), x);
    return 0.5f * x * (1.0f + er);
}

// ---- stats helpers ----------------------------------------------------------
__device__ __forceinline__ void stage_h(float* hS, int tid, const float (&h)[32]) {
    float4* d = reinterpret_cast<float4*>(hS + tid * HST);
#pragma unroll
    for (int k = 0; k < 8; k++)
        d[k] = make_float4(h[4 * k], h[4 * k + 1], h[4 * k + 2], h[4 * k + 3]);
}

// thread owns M row r (head=r>>3, d=r&7) over token-quarter q
__device__ __forceinline__ void accum_stats(const float* hS, int r, int q,
        u64& m0, u64& m1, u64& m2, u64& m3, float& sacc) {
    const float* p = hS + q * 32 * HST;
    const int eoff = (r & 24);  // head*8
#pragma unroll 4
    for (int s = 0; s < 32; s++) {
        float ed = __expf(p[r]);
        ulonglong2 hv = *reinterpret_cast<const ulonglong2*>(p + eoff);
        ulonglong2 hw = *reinterpret_cast<const ulonglong2*>(p + eoff + 4);
        u64 e2 = dup2(ed);
        fma2(m0, e2, hv.x); fma2(m1, e2, hv.y);
        fma2(m2, e2, hw.x); fma2(m3, e2, hw.y);
        sacc += ed;
        p += HST;
    }
}

// reduce 4 quarters via smem (red aliases hS), write chunk partial to gout
__device__ __forceinline__ void writeout_stats(float* red, float* gout, int tid,
        u64 m0, u64 m1, u64 m2, u64 m3, float sacc) {
    int r = tid & 31, q = tid >> 5;
    float2 a = unpk(m0), b = unpk(m1), c = unpk(m2), d = unpk(m3);
    float4* dst = reinterpret_cast<float4*>(red + q * 288 + r * 8);
    dst[0] = make_float4(a.x, a.y, b.x, b.y);
    dst[1] = make_float4(c.x, c.y, d.x, d.y);
    red[q * 288 + 256 + r] = sacc;
    __syncthreads();
    float M0 = red[tid] + red[288 + tid] + red[576 + tid] + red[864 + tid];
    float M1 = red[128 + tid] + red[416 + tid] + red[704 + tid] + red[992 + tid];
    gout[32 + tid] = M0;
    gout[160 + tid] = M1;
    if (tid < 32)
        gout[tid] = red[256 + tid] + red[544 + tid] + red[832 + tid] + red[1120 + tid];
}

// ---------------------------------------------------------------------------
// Kernel 1: stats over raw x -> g_partA
// ---------------------------------------------------------------------------
__global__ __launch_bounds__(NTH) void stats_x_kernel(const float* __restrict__ x) {
    __shared__ __align__(16) float hS[NTH * HST];
    int tid = threadIdx.x, b = blockIdx.y, ch = blockIdx.x;
    int r = tid & 31, q = tid >> 5;
    const float* xb = x + (size_t)b * Cn * Ln + ch * CHT;
    u64 m0 = 0, m1 = 0, m2 = 0, m3 = 0; float sacc = 0.f;
    for (int g = 0; g < NGR; g++) {
        int l = g * NTH + tid;
        float h[32];
#pragma unroll
        for (int c = 0; c < 32; c++) h[c] = xb[(size_t)c * Ln + l];
        stage_h(hS, tid, h);
        __syncthreads();
        accum_stats(hS, r, q, m0, m1, m2, m3, sacc);
        __syncthreads();
    }
    writeout_stats(hS, g_partA + (size_t)(b * NCH + ch) * 288, tid, m0, m1, m2, m3, sacc);
}

// ---------------------------------------------------------------------------
// Kernel 2: token pass. Prologue folds the partial-combine (kv). Body: attn,
// FC1+GELU, FC2+GELU, then next-block stats (or pool partials for LAST).
// ---------------------------------------------------------------------------
template <bool FROM_X, bool LAST, int IN_A>
__global__ __launch_bounds__(NTH) void token_kernel(
        const float* __restrict__ xin,
        const float* __restrict__ W1, const float* __restrict__ b1,
        const float* __restrict__ W2, const float* __restrict__ b2) {
    __shared__ __align__(16) float hS[NTH * HST];
    __shared__ __align__(16) float sW1[1024], sW2[1024], skv[256], sS[32], sb1[32], sb2[32];
    int tid = threadIdx.x, b = blockIdx.y, ch = blockIdx.x;
    int r = tid & 31, q = tid >> 5;

    const float* pin = IN_A ? g_partA : g_partB;
    float* pout = IN_A ? g_partB : g_partA;

    // prologue: combine chunk partials -> kv; load weights
    const float* pp = pin + (size_t)b * NCH * 288;
    float m0p = 0.f, m1p = 0.f;
#pragma unroll 4
    for (int c2 = 0; c2 < NCH; c2++) {
        m0p += pp[c2 * 288 + 32 + tid];
        m1p += pp[c2 * 288 + 160 + tid];
    }
    if (tid < 32) {
        float s = 0.f;
#pragma unroll 4
        for (int c2 = 0; c2 < NCH; c2++) s += pp[c2 * 288 + tid];
        sS[tid] = s;
        sb1[tid] = b1[tid];
        sb2[tid] = b2[tid];
    }
    for (int i = tid; i < 1024; i += NTH) { sW1[i] = W1[i]; sW2[i] = W2[i]; }
    __syncthreads();
    {
        int u0 = tid, u1 = tid + 128;
        int cd0 = ((u0 >> 6) << 3) | ((u0 >> 3) & 7);
        int cd1 = ((u1 >> 6) << 3) | ((u1 >> 3) & 7);
        skv[u0] = m0p / sS[cd0];
        skv[u1] = m1p / sS[cd1];
    }
    __syncthreads();

    u64 m0 = 0, m1 = 0, m2 = 0, m3 = 0; float sacc = 0.f, pacc = 0.f;
    const float* inb = FROM_X ? (xin + (size_t)b * Cn * Ln + ch * CHT)
                              : (g_h + (size_t)b * Cn * Ln + ch * CHT);
    float* outb = g_h + (size_t)b * Cn * Ln + ch * CHT;

    for (int g = 0; g < NGR; g++) {
        int l = g * NTH + tid;
        float h[32];
#pragma unroll
        for (int c = 0; c < 32; c++) h[c] = inb[(size_t)c * Ln + l];

        // ---- attention: q-softmax over dh (no max; bounded), @ kv ----
#pragma unroll
        for (int hd = 0; hd < 4; hd++) {
            float es[8]; float sum = 0.f;
#pragma unroll
            for (int d = 0; d < 8; d++) { es[d] = __expf(h[hd * 8 + d]); sum += es[d]; }
            u64 a0 = 0, a1 = 0, a2 = 0, a3 = 0;
#pragma unroll
            for (int d = 0; d < 8; d++) {
                const ulonglong2* kr = reinterpret_cast<const ulonglong2*>(&skv[hd * 64 + d * 8]);
                ulonglong2 k0 = kr[0], k1 = kr[1];
                u64 e2 = dup2(es[d]);
                fma2(a0, e2, k0.x); fma2(a1, e2, k0.y);
                fma2(a2, e2, k1.x); fma2(a3, e2, k1.y);
            }
            float inv = frcp(sum);
            float2 u;
            u = unpk(a0); h[hd * 8 + 0] = u.x * inv; h[hd * 8 + 1] = u.y * inv;
            u = unpk(a1); h[hd * 8 + 2] = u.x * inv; h[hd * 8 + 3] = u.y * inv;
            u = unpk(a2); h[hd * 8 + 4] = u.x * inv; h[hd * 8 + 5] = u.y * inv;
            u = unpk(a3); h[hd * 8 + 6] = u.x * inv; h[hd * 8 + 7] = u.y * inv;
        }

        // ---- FC1 + GELU (fma2 over j-pairs) ----
        u64 acc[16];
        {
            const ulonglong2* bb = reinterpret_cast<const ulonglong2*>(sb1);
#pragma unroll
            for (int k = 0; k < 8; k++) { ulonglong2 v = bb[k]; acc[2 * k] = v.x; acc[2 * k + 1] = v.y; }
        }
#pragma unroll
        for (int i = 0; i < 32; i++) {
            u64 ai = dup2(h[i]);
            const ulonglong2* wr = reinterpret_cast<const ulonglong2*>(&sW1[i * 32]);
#pragma unroll
            for (int k = 0; k < 8; k++) {
                ulonglong2 w = wr[k];
                fma2(acc[2 * k], ai, w.x);
                fma2(acc[2 * k + 1], ai, w.y);
            }
        }
        float f[32];
#pragma unroll
        for (int k = 0; k < 16; k++) {
            float2 u = unpk(acc[k]);
            f[2 * k] = gelu_f(u.x);
            f[2 * k + 1] = gelu_f(u.y);
        }

        // ---- FC2 + GELU ----
        {
            const ulonglong2* bb = reinterpret_cast<const ulonglong2*>(sb2);
#pragma unroll
            for (int k = 0; k < 8; k++) { ulonglong2 v = bb[k]; acc[2 * k] = v.x; acc[2 * k + 1] = v.y; }
        }
#pragma unroll
        for (int i = 0; i < 32; i++) {
            u64 ai = dup2(f[i]);
            const ulonglong2* wr = reinterpret_cast<const ulonglong2*>(&sW2[i * 32]);
#pragma unroll
            for (int k = 0; k < 8; k++) {
                ulonglong2 w = wr[k];
                fma2(acc[2 * k], ai, w.x);
                fma2(acc[2 * k + 1], ai, w.y);
            }
        }
#pragma unroll
        for (int k = 0; k < 16; k++) {
            float2 u = unpk(acc[k]);
            h[2 * k] = gelu_f(u.x);
            h[2 * k + 1] = gelu_f(u.y);
        }

        if (!LAST) {
#pragma unroll
            for (int c = 0; c < 32; c++) outb[(size_t)c * Ln + l] = h[c];
        }
        stage_h(hS, tid, h);
        __syncthreads();
        if (!LAST) {
            accum_stats(hS, r, q, m0, m1, m2, m3, sacc);
        } else {
            const float* p = hS + q * 32 * HST;
#pragma unroll 8
            for (int s = 0; s < 32; s++) { pacc += p[r]; p += HST; }
        }
        __syncthreads();
    }

    if (!LAST) {
        writeout_stats(hS, pout + (size_t)(b * NCH + ch) * 288, tid, m0, m1, m2, m3, sacc);
    } else {
        hS[q * 32 + r] = pacc;
        __syncthreads();
        if (tid < 32)
            g_pool[(size_t)(b * NCH + ch) * 32 + tid] =
                hS[tid] + hS[32 + tid] + hS[64 + tid] + hS[96 + tid];
    }
}

// ---------------------------------------------------------------------------
// Kernel 3: head (pool-finish, Linear, BN(eval), GELU, Linear)
// ---------------------------------------------------------------------------
__global__ __launch_bounds__(32) void final_kernel(
        const float* __restrict__ Wh, const float* __restrict__ bh,
        const float* __restrict__ gamma, const float* __restrict__ beta,
        const float* __restrict__ mu, const float* __restrict__ var,
        const float* __restrict__ Wf, const float* __restrict__ bf,
        float* __restrict__ out) {
    int b = threadIdx.x;
    if (b >= Bn) return;
    float p[32];
#pragma unroll
    for (int c = 0; c < 32; c++) {
        float sum = 0.f;
        for (int ch = 0; ch < NCH; ch++)
            sum += g_pool[(size_t)(b * NCH + ch) * 32 + c];
        p[c] = sum * (1.0f / (float)Ln);
    }
    float z[32];
#pragma unroll
    for (int j = 0; j < 32; j++) {
        float sv = bh[j];
#pragma unroll
        for (int c = 0; c < 32; c++) sv += p[c] * Wh[c * 32 + j];
        sv = (sv - mu[j]) * rsqrtf(var[j] + 1e-5f) * gamma[j] + beta[j];
        z[j] = 0.5f * sv * (1.0f + erff(sv * 0.7071067811865476f));
    }
    for (int k = 0; k < 10; k++) {
        float sv = bf[k];
#pragma unroll
        for (int j = 0; j < 32; j++) sv += z[j] * Wf[j * 10 + k];
        out[b * 10 + k] = sv;
    }
}

// ---------------------------------------------------------------------------
extern "C" void kernel_launch(void* const* d_in, const int* in_sizes, int n_in,
                              void* d_out, int out_size) {
    const float* x    = (const float*)d_in[0];
    const float* fcW1 = (const float*)d_in[1];
    const float* fcb1 = (const float*)d_in[2];
    const float* fcW2 = (const float*)d_in[3];
    const float* fcb2 = (const float*)d_in[4];
    const float* Wh   = (const float*)d_in[5];
    const float* bh   = (const float*)d_in[6];
    const float* gam  = (const float*)d_in[7];
    const float* bet  = (const float*)d_in[8];
    const float* mu   = (const float*)d_in[9];
    const float* var  = (const float*)d_in[10];
    const float* Wf   = (const float*)d_in[11];
    const float* bf   = (const float*)d_in[12];
    float* out = (float*)d_out;

    dim3 grid(NCH, Bn);
    stats_x_kernel<<<grid, NTH>>>(x);                                  // -> partA
    token_kernel<true,  false, 1><<<grid, NTH>>>(x, fcW1, fcb1, fcW2, fcb2);          // A->B
    token_kernel<false, false, 0><<<grid, NTH>>>(nullptr, fcW1 + 1024, fcb1 + 32,
                                                 fcW2 + 1024, fcb2 + 32);             // B->A
    token_kernel<false, true,  1><<<grid, NTH>>>(nullptr, fcW1 + 2048, fcb1 + 64,
                                                 fcW2 + 2048, fcb2 + 64);             // A->pool
    final_kernel<<<1, 32>>>(Wh, bh, gam, bet, mu, var, Wf, bf, out);
}